// round 4
// baseline (speedup 1.0000x reference)
#include <cuda_runtime.h>
#include <math.h>

// ---------------------------------------------------------------------------
// CrossAttention: B=4, Lq=Lk=2048, D=1024, H=16, DH=64
//   q = split(q_in @ Wq^T + bq); k = split(k_in @ Wk^T + bk); v = tanh(k_in @ Wv^T + bv)
//   logits = (q.k)*SCALE ; masked -> -10000 ; attn = softmax(logits/0.5)
//   topk: keep attn >= 205th largest per row
//   ctx = (attn @ v) * q ; out = ctx_flat @ Wo^T + bo
// Folding: stored logit = raw_dot * (SCALE*2) = raw*0.25, masked -> -20000.
// ---------------------------------------------------------------------------

#define NB   4
#define NH   16
#define LSEQ 2048
#define NDH  64
#define ND   1024
#define NBH  64           // NB*NH
#define TOPK 205          // ceil(2048*0.1)

// scratch (module-static device memory; allocation APIs are forbidden)
__device__ float g_q[8388608];        // [bh][2048][64]
__device__ float g_k[8388608];        // [bh][2048][64]
__device__ float g_v[8388608];        // [bh][2048][64]
__device__ float g_ctx[8388608];      // [B*Lq][1024]  (head-interleaved, gated by q)
__device__ float g_attn[268435456];   // [bh][2048][2048]  (1 GiB)

// ---- packed f32x2 helpers (sm_103a FFMA2 — only reachable via PTX) ----
__device__ __forceinline__ unsigned long long pk2(float lo, float hi) {
    unsigned long long r;
    asm("mov.b64 %0, {%1, %2};" : "=l"(r) : "f"(lo), "f"(hi));
    return r;
}
__device__ __forceinline__ void upk2(unsigned long long v, float &lo, float &hi) {
    asm("mov.b64 {%0, %1}, %2;" : "=f"(lo), "=f"(hi) : "l"(v));
}
__device__ __forceinline__ void fma2(unsigned long long &d,
                                     unsigned long long a, unsigned long long b) {
    asm("fma.rn.f32x2 %0, %1, %2, %3;" : "=l"(d) : "l"(a), "l"(b), "l"(d));
}

// ---------------------------------------------------------------------------
// Generic NT SGEMM: C[M,N] = A[M,K] @ W[N,K]^T + bias
// BM=128, BN=128, BK=16, 256 threads, 8x8 micro-tile (as 8x4 f32x2 pairs).
// mode 0: plain store to out[m*N + n]
// mode 1: split-head store  out[((b*16+h)*Lseq + l)*64 + dh]
// mode 2: split-head store with tanh
// Requires M%128==0, N%128==0, K%16==0 (true for all uses here).
// ---------------------------------------------------------------------------
__global__ void __launch_bounds__(256, 2)
sgemm_nt(const float* __restrict__ A, const float* __restrict__ W,
         const float* __restrict__ bias, float* __restrict__ outp,
         int M, int N, int K, int mode, int Lseq)
{
    __shared__ float As[16][132];
    __shared__ float Bs[16][132];

    const int tid  = threadIdx.x;
    const int m0   = blockIdx.y * 128;
    const int n0   = blockIdx.x * 128;
    const int ty   = tid >> 4;        // 0..15 -> rows ty*8..+7
    const int tx   = tid & 15;        // 0..15 -> cols tx*8..+7
    const int lrow = tid >> 1;        // 0..127
    const int lc   = (tid & 1) * 8;   // 0 or 8

    const float* Ap = A + (size_t)(m0 + lrow) * K + lc;
    const float* Wp = W + (size_t)(n0 + lrow) * K + lc;

    float4 a0 = *(const float4*)(Ap);
    float4 a1 = *(const float4*)(Ap + 4);
    float4 w0 = *(const float4*)(Wp);
    float4 w1 = *(const float4*)(Wp + 4);

    unsigned long long acc[8][4];
#pragma unroll
    for (int i = 0; i < 8; i++)
#pragma unroll
        for (int j = 0; j < 4; j++) acc[i][j] = 0ull;

    const int nch = K >> 4;
    for (int c = 0; c < nch; c++) {
        __syncthreads();
        As[lc+0][lrow]=a0.x; As[lc+1][lrow]=a0.y; As[lc+2][lrow]=a0.z; As[lc+3][lrow]=a0.w;
        As[lc+4][lrow]=a1.x; As[lc+5][lrow]=a1.y; As[lc+6][lrow]=a1.z; As[lc+7][lrow]=a1.w;
        Bs[lc+0][lrow]=w0.x; Bs[lc+1][lrow]=w0.y; Bs[lc+2][lrow]=w0.z; Bs[lc+3][lrow]=w0.w;
        Bs[lc+4][lrow]=w1.x; Bs[lc+5][lrow]=w1.y; Bs[lc+6][lrow]=w1.z; Bs[lc+7][lrow]=w1.w;
        __syncthreads();
        if (c + 1 < nch) {
            const float* ap = Ap + (c + 1) * 16;
            const float* wp = Wp + (c + 1) * 16;
            a0 = *(const float4*)ap;       a1 = *(const float4*)(ap + 4);
            w0 = *(const float4*)wp;       w1 = *(const float4*)(wp + 4);
        }
#pragma unroll
        for (int kk = 0; kk < 16; kk++) {
            const float4 af0 = *(const float4*)&As[kk][ty * 8];
            const float4 af1 = *(const float4*)&As[kk][ty * 8 + 4];
            const float4 bf0 = *(const float4*)&Bs[kk][tx * 8];
            const float4 bf1 = *(const float4*)&Bs[kk][tx * 8 + 4];
            const unsigned long long bp0 = pk2(bf0.x, bf0.y);
            const unsigned long long bp1 = pk2(bf0.z, bf0.w);
            const unsigned long long bp2 = pk2(bf1.x, bf1.y);
            const unsigned long long bp3 = pk2(bf1.z, bf1.w);
            const float av[8] = {af0.x, af0.y, af0.z, af0.w, af1.x, af1.y, af1.z, af1.w};
#pragma unroll
            for (int i = 0; i < 8; i++) {
                const unsigned long long ad = pk2(av[i], av[i]);
                fma2(acc[i][0], ad, bp0);
                fma2(acc[i][1], ad, bp1);
                fma2(acc[i][2], ad, bp2);
                fma2(acc[i][3], ad, bp3);
            }
        }
    }

#pragma unroll
    for (int i = 0; i < 8; i++) {
        const int m = m0 + ty * 8 + i;
#pragma unroll
        for (int j = 0; j < 4; j++) {
            float c0, c1;
            upk2(acc[i][j], c0, c1);
            const int n = n0 + tx * 8 + j * 2;
            c0 += bias[n];
            c1 += bias[n + 1];
            if (mode == 0) {
                outp[(size_t)m * N + n]     = c0;
                outp[(size_t)m * N + n + 1] = c1;
            } else {
                if (mode == 2) { c0 = tanhf(c0); c1 = tanhf(c1); }
                const int b = m / Lseq, l = m - b * Lseq;
                const int h = n >> 6, dh = n & 63;
                const size_t o = (((size_t)(b * NH + h)) * Lseq + l) * NDH + dh;
                outp[o]     = c0;
                outp[o + 1] = c1;
            }
        }
    }
}

// ---------------------------------------------------------------------------
// logits: per bh,  L[2048,2048] = q[2048,64] @ k[2048,64]^T ; scale+mask;
// writes pre-softmax logits (already /0.5 folded) into g_attn.
// ---------------------------------------------------------------------------
__global__ void __launch_bounds__(256, 2)
logits_kernel(const int* __restrict__ mask)
{
    __shared__ float As[16][132];
    __shared__ float Bs[16][132];

    const int tid  = threadIdx.x;
    const int bh   = blockIdx.z;
    const int m0   = blockIdx.y * 128;
    const int n0   = blockIdx.x * 128;
    const int ty   = tid >> 4;
    const int tx   = tid & 15;
    const int lrow = tid >> 1;
    const int lc   = (tid & 1) * 8;

    const float* Ap = g_q + (size_t)bh * LSEQ * NDH + (size_t)(m0 + lrow) * NDH + lc;
    const float* Wp = g_k + (size_t)bh * LSEQ * NDH + (size_t)(n0 + lrow) * NDH + lc;

    float4 a0 = *(const float4*)(Ap);
    float4 a1 = *(const float4*)(Ap + 4);
    float4 w0 = *(const float4*)(Wp);
    float4 w1 = *(const float4*)(Wp + 4);

    unsigned long long acc[8][4];
#pragma unroll
    for (int i = 0; i < 8; i++)
#pragma unroll
        for (int j = 0; j < 4; j++) acc[i][j] = 0ull;

#pragma unroll
    for (int c = 0; c < 4; c++) {
        __syncthreads();
        As[lc+0][lrow]=a0.x; As[lc+1][lrow]=a0.y; As[lc+2][lrow]=a0.z; As[lc+3][lrow]=a0.w;
        As[lc+4][lrow]=a1.x; As[lc+5][lrow]=a1.y; As[lc+6][lrow]=a1.z; As[lc+7][lrow]=a1.w;
        Bs[lc+0][lrow]=w0.x; Bs[lc+1][lrow]=w0.y; Bs[lc+2][lrow]=w0.z; Bs[lc+3][lrow]=w0.w;
        Bs[lc+4][lrow]=w1.x; Bs[lc+5][lrow]=w1.y; Bs[lc+6][lrow]=w1.z; Bs[lc+7][lrow]=w1.w;
        __syncthreads();
        if (c < 3) {
            const float* ap = Ap + (c + 1) * 16;
            const float* wp = Wp + (c + 1) * 16;
            a0 = *(const float4*)ap;   a1 = *(const float4*)(ap + 4);
            w0 = *(const float4*)wp;   w1 = *(const float4*)(wp + 4);
        }
#pragma unroll
        for (int kk = 0; kk < 16; kk++) {
            const float4 af0 = *(const float4*)&As[kk][ty * 8];
            const float4 af1 = *(const float4*)&As[kk][ty * 8 + 4];
            const float4 bf0 = *(const float4*)&Bs[kk][tx * 8];
            const float4 bf1 = *(const float4*)&Bs[kk][tx * 8 + 4];
            const unsigned long long bp0 = pk2(bf0.x, bf0.y);
            const unsigned long long bp1 = pk2(bf0.z, bf0.w);
            const unsigned long long bp2 = pk2(bf1.x, bf1.y);
            const unsigned long long bp3 = pk2(bf1.z, bf1.w);
            const float av[8] = {af0.x, af0.y, af0.z, af0.w, af1.x, af1.y, af1.z, af1.w};
#pragma unroll
            for (int i = 0; i < 8; i++) {
                const unsigned long long ad = pk2(av[i], av[i]);
                fma2(acc[i][0], ad, bp0);
                fma2(acc[i][1], ad, bp1);
                fma2(acc[i][2], ad, bp2);
                fma2(acc[i][3], ad, bp3);
            }
        }
    }

    const int b = bh >> 4;
    const int* mrow = mask + b * LSEQ;
#pragma unroll
    for (int i = 0; i < 8; i++) {
        const int m = m0 + ty * 8 + i;
        float* orow = g_attn + ((size_t)bh * LSEQ + m) * LSEQ;
#pragma unroll
        for (int j = 0; j < 4; j++) {
            float c0, c1;
            upk2(acc[i][j], c0, c1);
            const int n = n0 + tx * 8 + j * 2;
            orow[n]     = mrow[n]     ? -20000.0f : c0 * 0.25f;  // SCALE*2 = 0.25
            orow[n + 1] = mrow[n + 1] ? -20000.0f : c1 * 0.25f;
        }
    }
}

// ---------------------------------------------------------------------------
// softmax + exact top-k threshold mask, per row of g_attn (in place).
// One CTA per row; 4-pass MSD radix select on float bits (all values >= 0).
// ---------------------------------------------------------------------------
__global__ void __launch_bounds__(256)
softmax_topk_kernel()
{
    __shared__ float p[LSEQ];
    __shared__ float red[256];
    __shared__ unsigned int hist[256];
    __shared__ unsigned int s_pref;
    __shared__ int s_r;

    const int tid = threadIdx.x;
    float* g = g_attn + (size_t)blockIdx.x * LSEQ;

    float mx = -1e30f;
    for (int i = tid; i < LSEQ; i += 256) {
        const float v = g[i];
        p[i] = v;
        mx = fmaxf(mx, v);
    }
    red[tid] = mx;
    __syncthreads();
    for (int s = 128; s > 0; s >>= 1) {
        if (tid < s) red[tid] = fmaxf(red[tid], red[tid + s]);
        __syncthreads();
    }
    const float m = red[0];
    __syncthreads();

    float sum = 0.0f;
    for (int i = tid; i < LSEQ; i += 256) {
        const float e = expf(p[i] - m);
        p[i] = e;
        sum += e;
    }
    red[tid] = sum;
    __syncthreads();
    for (int s = 128; s > 0; s >>= 1) {
        if (tid < s) red[tid] += red[tid + s];
        __syncthreads();
    }
    const float inv = 1.0f / red[0];
    for (int i = tid; i < LSEQ; i += 256) p[i] *= inv;

    if (tid == 0) { s_pref = 0u; s_r = TOPK; }
    __syncthreads();

    const unsigned int pmasks[4] = {0u, 0xFF000000u, 0xFFFF0000u, 0xFFFFFF00u};
#pragma unroll
    for (int pass = 0; pass < 4; pass++) {
        const int shift = 24 - pass * 8;
        hist[tid] = 0u;
        __syncthreads();
        const unsigned int pmask = pmasks[pass];
        const unsigned int pref  = s_pref;
        for (int i = tid; i < LSEQ; i += 256) {
            const unsigned int u = __float_as_uint(p[i]);
            if ((u & pmask) == pref) atomicAdd(&hist[(u >> shift) & 255], 1u);
        }
        __syncthreads();
        if (tid == 0) {
            const int rr = s_r;
            unsigned int cum = 0;
            int d = 255;
            for (; d > 0; d--) {
                const unsigned int cc = hist[d];
                if (cum + cc >= (unsigned int)rr) break;
                cum += cc;
            }
            s_pref = pref | ((unsigned int)d << shift);
            s_r = rr - (int)cum;
        }
        __syncthreads();
    }

    const float thr = __uint_as_float(s_pref);
    for (int i = tid; i < LSEQ; i += 256) {
        const float v = p[i];
        g[i] = (v >= thr) ? v : 0.0f;
    }
}

// ---------------------------------------------------------------------------
// ctx: per bh, C[2048,64] = attn[2048,2048] @ v[2048,64]; epilogue *= q,
// stored head-interleaved into g_ctx[B*Lq, 1024].
// BM=128, BN=64, BK=16, 256 threads, 8x4 micro.
// ---------------------------------------------------------------------------
__global__ void __launch_bounds__(256, 2)
ctx_kernel()
{
    __shared__ float As[16][132];
    __shared__ float Bs[16][68];

    const int tid  = threadIdx.x;
    const int bh   = blockIdx.y;
    const int m0   = blockIdx.x * 128;
    const int ty   = tid >> 4;        // rows ty*8..+7
    const int tx   = tid & 15;        // cols tx*4..+3
    const int lrow = tid >> 1;
    const int lc   = (tid & 1) * 8;
    const int vkr  = tid >> 4;        // 0..15
    const int vc   = (tid & 15) * 4;  // 0..60

    const float* Ap = g_attn + ((size_t)bh * LSEQ + m0 + lrow) * LSEQ + lc;
    const float* Vp = g_v + (size_t)bh * LSEQ * NDH + (size_t)vkr * NDH + vc;

    float4 a0 = *(const float4*)(Ap);
    float4 a1 = *(const float4*)(Ap + 4);
    float4 b0 = *(const float4*)(Vp);

    unsigned long long acc[8][2];
#pragma unroll
    for (int i = 0; i < 8; i++) { acc[i][0] = 0ull; acc[i][1] = 0ull; }

    for (int c = 0; c < 128; c++) {
        __syncthreads();
        As[lc+0][lrow]=a0.x; As[lc+1][lrow]=a0.y; As[lc+2][lrow]=a0.z; As[lc+3][lrow]=a0.w;
        As[lc+4][lrow]=a1.x; As[lc+5][lrow]=a1.y; As[lc+6][lrow]=a1.z; As[lc+7][lrow]=a1.w;
        *(float4*)&Bs[vkr][vc] = b0;
        __syncthreads();
        if (c + 1 < 128) {
            const float* ap = Ap + (c + 1) * 16;
            a0 = *(const float4*)ap;
            a1 = *(const float4*)(ap + 4);
            b0 = *(const float4*)(Vp + (size_t)(c + 1) * 16 * NDH);
        }
#pragma unroll
        for (int kk = 0; kk < 16; kk++) {
            const float4 af0 = *(const float4*)&As[kk][ty * 8];
            const float4 af1 = *(const float4*)&As[kk][ty * 8 + 4];
            const float4 bf  = *(const float4*)&Bs[kk][tx * 4];
            const unsigned long long bp0 = pk2(bf.x, bf.y);
            const unsigned long long bp1 = pk2(bf.z, bf.w);
            const float av[8] = {af0.x, af0.y, af0.z, af0.w, af1.x, af1.y, af1.z, af1.w};
#pragma unroll
            for (int i = 0; i < 8; i++) {
                const unsigned long long ad = pk2(av[i], av[i]);
                fma2(acc[i][0], ad, bp0);
                fma2(acc[i][1], ad, bp1);
            }
        }
    }

    const int b = bh >> 4, h = bh & 15;
#pragma unroll
    for (int i = 0; i < 8; i++) {
        const int m = m0 + ty * 8 + i;
        const float* qrow = g_q + ((size_t)bh * LSEQ + m) * NDH;
        float* crow = g_ctx + ((size_t)(b * LSEQ + m)) * ND + h * NDH;
#pragma unroll
        for (int j = 0; j < 2; j++) {
            float c0, c1;
            upk2(acc[i][j], c0, c1);
            const int n = tx * 4 + j * 2;
            crow[n]     = c0 * qrow[n];
            crow[n + 1] = c1 * qrow[n + 1];
        }
    }
}

// ---------------------------------------------------------------------------
extern "C" void kernel_launch(void* const* d_in, const int* in_sizes, int n_in,
                              void* d_out, int out_size)
{
    const float* q_in = (const float*)d_in[0];
    const float* k_in = (const float*)d_in[1];
    const float* Wq   = (const float*)d_in[2];
    const float* bq   = (const float*)d_in[3];
    const float* Wk   = (const float*)d_in[4];
    const float* bk   = (const float*)d_in[5];
    const float* Wv   = (const float*)d_in[6];
    const float* bv   = (const float*)d_in[7];
    const float* Wo   = (const float*)d_in[8];
    const float* bo   = (const float*)d_in[9];
    const int*   mask = (const int*)d_in[10];
    float* out = (float*)d_out;

    void *pq = 0, *pk = 0, *pv = 0, *pctx = 0;
    cudaGetSymbolAddress(&pq, g_q);
    cudaGetSymbolAddress(&pk, g_k);
    cudaGetSymbolAddress(&pv, g_v);
    cudaGetSymbolAddress(&pctx, g_ctx);

    const dim3 thr(256);
    const dim3 gp(ND / 128, (NB * LSEQ) / 128);          // (8, 64)

    sgemm_nt<<<gp, thr>>>(q_in, Wq, bq, (float*)pq, NB * LSEQ, ND, ND, 1, LSEQ);
    sgemm_nt<<<gp, thr>>>(k_in, Wk, bk, (float*)pk, NB * LSEQ, ND, ND, 1, LSEQ);
    sgemm_nt<<<gp, thr>>>(k_in, Wv, bv, (float*)pv, NB * LSEQ, ND, ND, 2, LSEQ);

    const dim3 gl(LSEQ / 128, LSEQ / 128, NBH);          // (16, 16, 64)
    logits_kernel<<<gl, thr>>>(mask);

    softmax_topk_kernel<<<NBH * LSEQ, thr>>>();          // 131072 rows

    const dim3 gc(LSEQ / 128, NBH);                      // (16, 64)
    ctx_kernel<<<gc, thr>>>();

    sgemm_nt<<<gp, thr>>>((const float*)pctx, Wo, bo, out, NB * LSEQ, ND, ND, 0, LSEQ);
}

// round 5
// speedup vs baseline: 1.1212x; 1.1212x over previous
#include <cuda_runtime.h>
#include <math.h>

#define NB   4
#define NH   16
#define LSEQ 2048
#define NDH  64
#define ND   1024
#define NBH  64
#define TOPK 205
#define PSTR 2052   // sP row stride (floats)

// scratch (static device memory; allocation APIs forbidden)
__device__ float g_q[8388608];        // [bh][2048][64]
__device__ float g_kT[8388608];       // [bh][64][2048]  (k transposed per head)
__device__ float g_v[8388608];        // [bh][2048][64]
__device__ float g_ctx[8388608];      // [B*Lq][1024]

typedef unsigned long long ull;
__device__ __forceinline__ ull pk2(float lo, float hi) {
    ull r; asm("mov.b64 %0, {%1, %2};" : "=l"(r) : "f"(lo), "f"(hi)); return r;
}
__device__ __forceinline__ void upk2(ull v, float &lo, float &hi) {
    asm("mov.b64 {%0, %1}, %2;" : "=f"(lo), "=f"(hi) : "l"(v));
}
__device__ __forceinline__ void fma2(ull &d, ull a, ull b) {
    asm("fma.rn.f32x2 %0, %1, %2, %3;" : "=l"(d) : "l"(a), "l"(b), "l"(d));
}

// ---------------------------------------------------------------------------
// NT SGEMM: C[M,N] = A[M,K] @ W[N,K]^T + bias.  BM=BN=128, BK=16, 256 thr.
// mode 0: plain  out[m*N+n]
// mode 1: split-head   out[((b*16+h)*L + l)*64 + dh]
// mode 2: split-head + tanh
// mode 3: split-head TRANSPOSED  out[((b*16+h)*64 + dh)*L + l]
// ---------------------------------------------------------------------------
__global__ void __launch_bounds__(256, 2)
sgemm_nt(const float* __restrict__ A, const float* __restrict__ W,
         const float* __restrict__ bias, float* __restrict__ outp,
         int M, int N, int K, int mode, int Lseq)
{
    __shared__ float As[16][132];
    __shared__ float Bs[16][132];

    const int tid  = threadIdx.x;
    const int m0   = blockIdx.y * 128;
    const int n0   = blockIdx.x * 128;
    const int ty   = tid >> 4;
    const int tx   = tid & 15;
    const int lrow = tid >> 1;
    const int lc   = (tid & 1) * 8;

    const float* Ap = A + (size_t)(m0 + lrow) * K + lc;
    const float* Wp = W + (size_t)(n0 + lrow) * K + lc;

    float4 a0 = *(const float4*)(Ap);
    float4 a1 = *(const float4*)(Ap + 4);
    float4 w0 = *(const float4*)(Wp);
    float4 w1 = *(const float4*)(Wp + 4);

    ull acc[8][4];
#pragma unroll
    for (int i = 0; i < 8; i++)
#pragma unroll
        for (int j = 0; j < 4; j++) acc[i][j] = 0ull;

    const int nch = K >> 4;
    for (int c = 0; c < nch; c++) {
        __syncthreads();
        As[lc+0][lrow]=a0.x; As[lc+1][lrow]=a0.y; As[lc+2][lrow]=a0.z; As[lc+3][lrow]=a0.w;
        As[lc+4][lrow]=a1.x; As[lc+5][lrow]=a1.y; As[lc+6][lrow]=a1.z; As[lc+7][lrow]=a1.w;
        Bs[lc+0][lrow]=w0.x; Bs[lc+1][lrow]=w0.y; Bs[lc+2][lrow]=w0.z; Bs[lc+3][lrow]=w0.w;
        Bs[lc+4][lrow]=w1.x; Bs[lc+5][lrow]=w1.y; Bs[lc+6][lrow]=w1.z; Bs[lc+7][lrow]=w1.w;
        __syncthreads();
        if (c + 1 < nch) {
            const float* ap = Ap + (c + 1) * 16;
            const float* wp = Wp + (c + 1) * 16;
            a0 = *(const float4*)ap;  a1 = *(const float4*)(ap + 4);
            w0 = *(const float4*)wp;  w1 = *(const float4*)(wp + 4);
        }
#pragma unroll
        for (int kk = 0; kk < 16; kk++) {
            const float4 af0 = *(const float4*)&As[kk][ty * 8];
            const float4 af1 = *(const float4*)&As[kk][ty * 8 + 4];
            const float4 bf0 = *(const float4*)&Bs[kk][tx * 8];
            const float4 bf1 = *(const float4*)&Bs[kk][tx * 8 + 4];
            const ull bp0 = pk2(bf0.x, bf0.y);
            const ull bp1 = pk2(bf0.z, bf0.w);
            const ull bp2 = pk2(bf1.x, bf1.y);
            const ull bp3 = pk2(bf1.z, bf1.w);
            const float av[8] = {af0.x, af0.y, af0.z, af0.w, af1.x, af1.y, af1.z, af1.w};
#pragma unroll
            for (int i = 0; i < 8; i++) {
                const ull ad = pk2(av[i], av[i]);
                fma2(acc[i][0], ad, bp0);
                fma2(acc[i][1], ad, bp1);
                fma2(acc[i][2], ad, bp2);
                fma2(acc[i][3], ad, bp3);
            }
        }
    }

#pragma unroll
    for (int i = 0; i < 8; i++) {
        const int m = m0 + ty * 8 + i;
#pragma unroll
        for (int j = 0; j < 4; j++) {
            float c0, c1;
            upk2(acc[i][j], c0, c1);
            const int n = n0 + tx * 8 + j * 2;
            c0 += bias[n];
            c1 += bias[n + 1];
            if (mode == 0) {
                outp[(size_t)m * N + n]     = c0;
                outp[(size_t)m * N + n + 1] = c1;
            } else if (mode == 3) {
                const int b = m / Lseq, l = m - b * Lseq;
                const int h = n >> 6, dh = n & 63;
                const size_t o = ((size_t)(b * NH + h) * NDH + dh) * Lseq + l;
                outp[o]        = c0;
                outp[o + Lseq] = c1;
            } else {
                if (mode == 2) { c0 = tanhf(c0); c1 = tanhf(c1); }
                const int b = m / Lseq, l = m - b * Lseq;
                const int h = n >> 6, dh = n & 63;
                const size_t o = (((size_t)(b * NH + h)) * Lseq + l) * NDH + dh;
                outp[o]     = c0;
                outp[o + 1] = c1;
            }
        }
    }
}

// ---------------------------------------------------------------------------
// Fused attention: per CTA = (bh, 16 q-rows). logits -> softmax -> exact
// top-k threshold -> ctx = attn@v * q.  Probs live in smem only.
// 512 threads, ~148 KB dynamic smem, 1 CTA/SM.
// ---------------------------------------------------------------------------
__global__ void __launch_bounds__(512, 1)
fused_attn(const int* __restrict__ mask)
{
    extern __shared__ float sm[];
    float* sP  = sm;                          // [16][PSTR]
    float* sQT = sm + 16 * PSTR;              // [64][16]  q transposed
    unsigned* hist = (unsigned*)(sm + 16 * PSTR + 1024);  // [16][256]

    const int tid = threadIdx.x;
    const int bh  = blockIdx.y;
    const int m0  = blockIdx.x * 16;
    const int b   = bh >> 4, h = bh & 15;

    // ---- phase 0: q tile, transposed into smem ----
    for (int i = tid; i < 1024; i += 512) {
        const int r = i >> 6, d = i & 63;
        sQT[d * 16 + r] = g_q[((size_t)bh * LSEQ + m0 + r) * NDH + d];
    }
    __syncthreads();

    // ---- phase 1: logits for cols [tid*4, tid*4+4), all 16 rows ----
    {
        const int n0 = tid * 4;
        const float* kb = g_kT + (size_t)bh * NDH * LSEQ + n0;
        ull acc[8][4];   // row-pair rp=(2rp,2rp+1) x col c
#pragma unroll
        for (int i = 0; i < 8; i++)
#pragma unroll
            for (int j = 0; j < 4; j++) acc[i][j] = 0ull;

        for (int d0 = 0; d0 < 64; d0 += 4) {
#pragma unroll
            for (int dd = 0; dd < 4; dd++) {
                const float4 kv = *(const float4*)(kb + (size_t)(d0 + dd) * LSEQ);
                const ull k0 = pk2(kv.x, kv.x);
                const ull k1 = pk2(kv.y, kv.y);
                const ull k2 = pk2(kv.z, kv.z);
                const ull k3 = pk2(kv.w, kv.w);
                const ull* qrow = (const ull*)&sQT[(d0 + dd) * 16];
#pragma unroll
                for (int rp = 0; rp < 8; rp++) {
                    const ull qq = qrow[rp];
                    fma2(acc[rp][0], qq, k0);
                    fma2(acc[rp][1], qq, k1);
                    fma2(acc[rp][2], qq, k2);
                    fma2(acc[rp][3], qq, k3);
                }
            }
        }

        const int4 mv = *(const int4*)(mask + b * LSEQ + n0);
        const int mk[4] = {mv.x, mv.y, mv.z, mv.w};
#pragma unroll
        for (int rp = 0; rp < 8; rp++) {
            float lo[4], hi[4];
#pragma unroll
            for (int c = 0; c < 4; c++) {
                upk2(acc[rp][c], lo[c], hi[c]);
                lo[c] = mk[c] ? -20000.0f : lo[c] * 0.25f;   // SCALE*2 folded
                hi[c] = mk[c] ? -20000.0f : hi[c] * 0.25f;
            }
            *(float4*)&sP[(2 * rp)     * PSTR + n0] = make_float4(lo[0], lo[1], lo[2], lo[3]);
            *(float4*)&sP[(2 * rp + 1) * PSTR + n0] = make_float4(hi[0], hi[1], hi[2], hi[3]);
        }
    }
    __syncthreads();

    // ---- phase 2: softmax + exact top-k threshold, one warp per row ----
    {
        const int w = tid >> 5, l = tid & 31;
        float* pr = sP + w * PSTR;

        float mx = -3.0e38f;
        for (int i = l; i < LSEQ; i += 32) mx = fmaxf(mx, pr[i]);
#pragma unroll
        for (int o = 16; o; o >>= 1) mx = fmaxf(mx, __shfl_xor_sync(0xffffffffu, mx, o));

        float s = 0.0f;
        for (int i = l; i < LSEQ; i += 32) { const float e = expf(pr[i] - mx); pr[i] = e; s += e; }
#pragma unroll
        for (int o = 16; o; o >>= 1) s += __shfl_xor_sync(0xffffffffu, s, o);
        const float inv = 1.0f / s;
        for (int i = l; i < LSEQ; i += 32) pr[i] *= inv;
        __syncwarp();

        unsigned* hw = hist + w * 256;
        unsigned pref = 0; int need = TOPK;
        const unsigned pmasks[4] = {0u, 0xFF000000u, 0xFFFF0000u, 0xFFFFFF00u};
#pragma unroll
        for (int pass = 0; pass < 4; pass++) {
            const int shift = 24 - pass * 8;
            const unsigned pmask = pmasks[pass];
            for (int bi = l; bi < 256; bi += 32) hw[bi] = 0u;
            __syncwarp();
            for (int i = l; i < LSEQ; i += 32) {
                const unsigned u = __float_as_uint(pr[i]);
                if ((u & pmask) == pref) atomicAdd(&hw[(u >> shift) & 255], 1u);
            }
            __syncwarp();
            if (l == 0) {
                unsigned cum = 0; int d = 255;
                for (; d > 0; d--) {
                    const unsigned cc = hw[d];
                    if (cum + cc >= (unsigned)need) break;
                    cum += cc;
                }
                pref |= (unsigned)d << shift;
                need -= (int)cum;
            }
            pref = __shfl_sync(0xffffffffu, pref, 0);
            need = __shfl_sync(0xffffffffu, need, 0);
            __syncwarp();
        }
        const float thr = __uint_as_float(pref);
        for (int i = l; i < LSEQ; i += 32) { const float v = pr[i]; pr[i] = (v >= thr) ? v : 0.0f; }
    }
    __syncthreads();

    // ---- phase 3: ctx = P @ v, gate by q ----
    {
        const int g = tid & 15;          // dh slice g*4..+3
        const int s = tid >> 4;          // n slot (0..31)
        const float* vb = g_v + (size_t)bh * LSEQ * NDH + g * 4;
        ull acc[16][2];
#pragma unroll
        for (int r = 0; r < 16; r++) { acc[r][0] = 0ull; acc[r][1] = 0ull; }

        for (int n = s; n < LSEQ; n += 32) {
            const float4 vv = *(const float4*)(vb + (size_t)n * NDH);
            const ull v01 = pk2(vv.x, vv.y);
            const ull v23 = pk2(vv.z, vv.w);
#pragma unroll
            for (int r = 0; r < 16; r++) {
                const float p = sP[r * PSTR + n];
                const ull pp = pk2(p, p);
                fma2(acc[r][0], pp, v01);
                fma2(acc[r][1], pp, v23);
            }
        }
        __syncthreads();                  // all reads of sP done

        float* sR = sm;                   // overlay partials on sP: [32][16][64]
#pragma unroll
        for (int r = 0; r < 16; r++) {
            float a0, a1, a2, a3;
            upk2(acc[r][0], a0, a1);
            upk2(acc[r][1], a2, a3);
            *(float4*)&sR[((s * 16 + r) << 6) + (g << 2)] = make_float4(a0, a1, a2, a3);
        }
        __syncthreads();

        for (int o = tid; o < 1024; o += 512) {
            float c = 0.0f;
#pragma unroll
            for (int s2 = 0; s2 < 32; s2++) c += sR[(s2 << 10) + o];
            const int r = o >> 6, dh = o & 63;
            c *= sQT[dh * 16 + r];
            g_ctx[((size_t)(b * LSEQ) + m0 + r) * ND + h * NDH + dh] = c;
        }
    }
}

// ---------------------------------------------------------------------------
extern "C" void kernel_launch(void* const* d_in, const int* in_sizes, int n_in,
                              void* d_out, int out_size)
{
    const float* q_in = (const float*)d_in[0];
    const float* k_in = (const float*)d_in[1];
    const float* Wq   = (const float*)d_in[2];
    const float* bq   = (const float*)d_in[3];
    const float* Wk   = (const float*)d_in[4];
    const float* bk   = (const float*)d_in[5];
    const float* Wv   = (const float*)d_in[6];
    const float* bv   = (const float*)d_in[7];
    const float* Wo   = (const float*)d_in[8];
    const float* bo   = (const float*)d_in[9];
    const int*   mask = (const int*)d_in[10];
    float* out = (float*)d_out;

    void *pq = 0, *pk = 0, *pv = 0, *pctx = 0;
    cudaGetSymbolAddress(&pq, g_q);
    cudaGetSymbolAddress(&pk, g_kT);
    cudaGetSymbolAddress(&pv, g_v);
    cudaGetSymbolAddress(&pctx, g_ctx);

    const int smemb = (16 * PSTR + 1024 + 16 * 256) * 4;   // 151808 B
    cudaFuncSetAttribute(fused_attn, cudaFuncAttributeMaxDynamicSharedMemorySize, smemb);

    const dim3 thr(256);
    const dim3 gp(ND / 128, (NB * LSEQ) / 128);            // (8, 64)

    sgemm_nt<<<gp, thr>>>(q_in, Wq, bq, (float*)pq, NB * LSEQ, ND, ND, 1, LSEQ);
    sgemm_nt<<<gp, thr>>>(k_in, Wk, bk, (float*)pk, NB * LSEQ, ND, ND, 3, LSEQ);
    sgemm_nt<<<gp, thr>>>(k_in, Wv, bv, (float*)pv, NB * LSEQ, ND, ND, 2, LSEQ);

    fused_attn<<<dim3(LSEQ / 16, NBH), 512, smemb>>>(mask);

    sgemm_nt<<<gp, thr>>>((const float*)pctx, Wo, bo, out, NB * LSEQ, ND, ND, 0, LSEQ);
}

// round 7
// speedup vs baseline: 1.3202x; 1.1776x over previous
#include <cuda_runtime.h>
#include <math.h>

#define NB   4
#define NH   16
#define LSEQ 2048
#define NDH  64
#define ND   1024
#define NBH  64
#define TOPK 205
#define PSTR 2052   // sP row stride (floats)

// scratch (static device memory; allocation APIs forbidden)
__device__ float g_q[8388608];        // [bh][2048][64]
__device__ float g_kT[8388608];       // [bh][64][2048]
__device__ float g_v[8388608];        // [bh][2048][64]
__device__ float g_ctx[8388608];      // [B*Lq][1024]

typedef unsigned long long ull;
__device__ __forceinline__ ull pk2(float lo, float hi) {
    ull r; asm("mov.b64 %0, {%1, %2};" : "=l"(r) : "f"(lo), "f"(hi)); return r;
}
__device__ __forceinline__ void upk2(ull v, float &lo, float &hi) {
    asm("mov.b64 {%0, %1}, %2;" : "=f"(lo), "=f"(hi) : "l"(v));
}
__device__ __forceinline__ void fma2(ull &d, ull a, ull b) {
    asm("fma.rn.f32x2 %0, %1, %2, %3;" : "=l"(d) : "l"(a), "l"(b), "l"(d));
}

// ---------------------------------------------------------------------------
// Double-buffered NT GEMM tile body: C[128,128] += A[M,K] @ W[N,K]^T + bias.
// BK=16, 256 threads, 8x8 micro-tile, one barrier per chunk, 2-chunk reg
// prefetch. mode: 0 plain / 1 split-head / 2 split-head+tanh / 3 split-head-T.
// ---------------------------------------------------------------------------
__device__ __forceinline__ void gemm_dbuf(
    const float* __restrict__ A, const float* __restrict__ W,
    const float* __restrict__ bias, float* __restrict__ outp,
    int N, int K, int mode, int Lseq, int m0, int n0,
    float As[2][16][132], float Bs[2][16][132])
{
    const int tid  = threadIdx.x;
    const int ty   = tid >> 4;
    const int tx   = tid & 15;
    const int lrow = tid >> 1;
    const int lc   = (tid & 1) * 8;

    const float* Ap = A + (size_t)(m0 + lrow) * K + lc;
    const float* Wp = W + (size_t)(n0 + lrow) * K + lc;

    ull acc[8][4];
#pragma unroll
    for (int i = 0; i < 8; i++)
#pragma unroll
        for (int j = 0; j < 4; j++) acc[i][j] = 0ull;

    const int nch = K >> 4;
    float4 a0 = *(const float4*)(Ap);
    float4 a1 = *(const float4*)(Ap + 4);
    float4 w0 = *(const float4*)(Wp);
    float4 w1 = *(const float4*)(Wp + 4);

    // store chunk 0 into buf 0
    As[0][lc+0][lrow]=a0.x; As[0][lc+1][lrow]=a0.y; As[0][lc+2][lrow]=a0.z; As[0][lc+3][lrow]=a0.w;
    As[0][lc+4][lrow]=a1.x; As[0][lc+5][lrow]=a1.y; As[0][lc+6][lrow]=a1.z; As[0][lc+7][lrow]=a1.w;
    Bs[0][lc+0][lrow]=w0.x; Bs[0][lc+1][lrow]=w0.y; Bs[0][lc+2][lrow]=w0.z; Bs[0][lc+3][lrow]=w0.w;
    Bs[0][lc+4][lrow]=w1.x; Bs[0][lc+5][lrow]=w1.y; Bs[0][lc+6][lrow]=w1.z; Bs[0][lc+7][lrow]=w1.w;
    if (nch > 1) {
        a0 = *(const float4*)(Ap + 16); a1 = *(const float4*)(Ap + 20);
        w0 = *(const float4*)(Wp + 16); w1 = *(const float4*)(Wp + 20);
    }
    __syncthreads();

    for (int c = 0; c < nch; c++) {
        const int cur = c & 1;
        if (c + 1 < nch) {
            const int nb = cur ^ 1;
            As[nb][lc+0][lrow]=a0.x; As[nb][lc+1][lrow]=a0.y; As[nb][lc+2][lrow]=a0.z; As[nb][lc+3][lrow]=a0.w;
            As[nb][lc+4][lrow]=a1.x; As[nb][lc+5][lrow]=a1.y; As[nb][lc+6][lrow]=a1.z; As[nb][lc+7][lrow]=a1.w;
            Bs[nb][lc+0][lrow]=w0.x; Bs[nb][lc+1][lrow]=w0.y; Bs[nb][lc+2][lrow]=w0.z; Bs[nb][lc+3][lrow]=w0.w;
            Bs[nb][lc+4][lrow]=w1.x; Bs[nb][lc+5][lrow]=w1.y; Bs[nb][lc+6][lrow]=w1.z; Bs[nb][lc+7][lrow]=w1.w;
            if (c + 2 < nch) {
                const float* ap = Ap + (c + 2) * 16;
                const float* wp = Wp + (c + 2) * 16;
                a0 = *(const float4*)ap;  a1 = *(const float4*)(ap + 4);
                w0 = *(const float4*)wp;  w1 = *(const float4*)(wp + 4);
            }
        }
#pragma unroll
        for (int kk = 0; kk < 16; kk++) {
            const float4 af0 = *(const float4*)&As[cur][kk][ty * 8];
            const float4 af1 = *(const float4*)&As[cur][kk][ty * 8 + 4];
            const float4 bf0 = *(const float4*)&Bs[cur][kk][tx * 8];
            const float4 bf1 = *(const float4*)&Bs[cur][kk][tx * 8 + 4];
            const ull bp0 = pk2(bf0.x, bf0.y);
            const ull bp1 = pk2(bf0.z, bf0.w);
            const ull bp2 = pk2(bf1.x, bf1.y);
            const ull bp3 = pk2(bf1.z, bf1.w);
            const float av[8] = {af0.x, af0.y, af0.z, af0.w, af1.x, af1.y, af1.z, af1.w};
#pragma unroll
            for (int i = 0; i < 8; i++) {
                const ull ad = pk2(av[i], av[i]);
                fma2(acc[i][0], ad, bp0);
                fma2(acc[i][1], ad, bp1);
                fma2(acc[i][2], ad, bp2);
                fma2(acc[i][3], ad, bp3);
            }
        }
        __syncthreads();
    }

#pragma unroll
    for (int i = 0; i < 8; i++) {
        const int m = m0 + ty * 8 + i;
#pragma unroll
        for (int j = 0; j < 4; j++) {
            float c0, c1;
            upk2(acc[i][j], c0, c1);
            const int n = n0 + tx * 8 + j * 2;
            c0 += bias[n];
            c1 += bias[n + 1];
            if (mode == 0) {
                outp[(size_t)m * N + n]     = c0;
                outp[(size_t)m * N + n + 1] = c1;
            } else if (mode == 3) {
                const int b = m / Lseq, l = m - b * Lseq;
                const int h = n >> 6, dh = n & 63;
                const size_t o = ((size_t)(b * NH + h) * NDH + dh) * Lseq + l;
                outp[o]        = c0;
                outp[o + Lseq] = c1;
            } else {
                if (mode == 2) { c0 = tanhf(c0); c1 = tanhf(c1); }
                const int b = m / Lseq, l = m - b * Lseq;
                const int h = n >> 6, dh = n & 63;
                const size_t o = (((size_t)(b * NH + h)) * Lseq + l) * NDH + dh;
                outp[o]     = c0;
                outp[o + 1] = c1;
            }
        }
    }
}

// q/k/v projections merged into one launch (z selects); kills wave-tail waste.
__global__ void __launch_bounds__(256, 2)
proj_qkv(const float* __restrict__ q_in, const float* __restrict__ k_in,
         const float* __restrict__ Wq, const float* __restrict__ bq,
         const float* __restrict__ Wk, const float* __restrict__ bk,
         const float* __restrict__ Wv, const float* __restrict__ bv,
         float* pq, float* pkT, float* pv)
{
    __shared__ float As[2][16][132];
    __shared__ float Bs[2][16][132];
    const int z = blockIdx.z;
    const float* A    = (z == 0) ? q_in : k_in;
    const float* W    = (z == 0) ? Wq : (z == 1) ? Wk : Wv;
    const float* bias = (z == 0) ? bq : (z == 1) ? bk : bv;
    float* outp       = (z == 0) ? pq : (z == 1) ? pkT : pv;
    const int mode    = (z == 0) ? 1 : (z == 1) ? 3 : 2;
    gemm_dbuf(A, W, bias, outp, ND, ND, mode, LSEQ,
              blockIdx.y * 128, blockIdx.x * 128, As, Bs);
}

__global__ void __launch_bounds__(256, 2)
out_proj(const float* __restrict__ A, const float* __restrict__ W,
         const float* __restrict__ bias, float* __restrict__ outp)
{
    __shared__ float As[2][16][132];
    __shared__ float Bs[2][16][132];
    gemm_dbuf(A, W, bias, outp, ND, ND, 0, LSEQ,
              blockIdx.y * 128, blockIdx.x * 128, As, Bs);
}

// ---------------------------------------------------------------------------
// Fused attention: CTA = (bh, 16 q-rows). logits -> softmax -> exact top-k
// -> ctx = attn@v * q.  Probs live in smem only. Reg-prefetched k/v streams.
// ---------------------------------------------------------------------------
__global__ void __launch_bounds__(512, 1)
fused_attn(const int* __restrict__ mask)
{
    extern __shared__ float sm[];
    float* sP  = sm;                                      // [16][PSTR]
    float* sQT = sm + 16 * PSTR;                          // [64][16]
    unsigned* hist = (unsigned*)(sm + 16 * PSTR + 1024);  // [16][256]

    const int tid = threadIdx.x;
    const int bh  = blockIdx.y;
    const int m0  = blockIdx.x * 16;
    const int b   = bh >> 4, h = bh & 15;

    // ---- phase 0: q tile, transposed into smem ----
    for (int i = tid; i < 1024; i += 512) {
        const int r = i >> 6, d = i & 63;
        sQT[d * 16 + r] = g_q[((size_t)bh * LSEQ + m0 + r) * NDH + d];
    }
    __syncthreads();

    // ---- phase 1: logits for cols [tid*4, tid*4+4), all 16 rows ----
    {
        const int n0 = tid * 4;
        const float* kb = g_kT + (size_t)bh * NDH * LSEQ + n0;
        ull acc[8][4];
#pragma unroll
        for (int i = 0; i < 8; i++)
#pragma unroll
            for (int j = 0; j < 4; j++) acc[i][j] = 0ull;

#define PROC1(KV, D) do {                                                   \
        const ull k0 = pk2((KV).x, (KV).x);                                 \
        const ull k1 = pk2((KV).y, (KV).y);                                 \
        const ull k2 = pk2((KV).z, (KV).z);                                 \
        const ull k3 = pk2((KV).w, (KV).w);                                 \
        const ull* qrow = (const ull*)&sQT[(D) * 16];                       \
        _Pragma("unroll")                                                   \
        for (int rp = 0; rp < 8; rp++) {                                    \
            const ull qq = qrow[rp];                                        \
            fma2(acc[rp][0], qq, k0);                                       \
            fma2(acc[rp][1], qq, k1);                                       \
            fma2(acc[rp][2], qq, k2);                                       \
            fma2(acc[rp][3], qq, k3);                                       \
        } } while (0)

        float4 c0 = *(const float4*)(kb);
        float4 c1 = *(const float4*)(kb + LSEQ);
        for (int d0 = 0; d0 < 62; d0 += 2) {
            const float4 nx0 = *(const float4*)(kb + (size_t)(d0 + 2) * LSEQ);
            const float4 nx1 = *(const float4*)(kb + (size_t)(d0 + 3) * LSEQ);
            PROC1(c0, d0);
            PROC1(c1, d0 + 1);
            c0 = nx0; c1 = nx1;
        }
        PROC1(c0, 62);
        PROC1(c1, 63);
#undef PROC1

        const int4 mv = *(const int4*)(mask + b * LSEQ + n0);
        const int mk[4] = {mv.x, mv.y, mv.z, mv.w};
#pragma unroll
        for (int rp = 0; rp < 8; rp++) {
            float lo[4], hi[4];
#pragma unroll
            for (int c = 0; c < 4; c++) {
                upk2(acc[rp][c], lo[c], hi[c]);
                lo[c] = mk[c] ? -20000.0f : lo[c] * 0.25f;   // SCALE*2 folded
                hi[c] = mk[c] ? -20000.0f : hi[c] * 0.25f;
            }
            *(float4*)&sP[(2 * rp)     * PSTR + n0] = make_float4(lo[0], lo[1], lo[2], lo[3]);
            *(float4*)&sP[(2 * rp + 1) * PSTR + n0] = make_float4(hi[0], hi[1], hi[2], hi[3]);
        }
    }
    __syncthreads();

    // ---- phase 2: softmax + exact top-k threshold, one warp per row ----
    {
        const int w = tid >> 5, l = tid & 31;
        float* pr = sP + w * PSTR;

        float mx = -3.0e38f;
        for (int i = l; i < LSEQ; i += 32) mx = fmaxf(mx, pr[i]);
#pragma unroll
        for (int o = 16; o; o >>= 1) mx = fmaxf(mx, __shfl_xor_sync(0xffffffffu, mx, o));

        float s = 0.0f;
        for (int i = l; i < LSEQ; i += 32) { const float e = expf(pr[i] - mx); pr[i] = e; s += e; }
#pragma unroll
        for (int o = 16; o; o >>= 1) s += __shfl_xor_sync(0xffffffffu, s, o);
        const float inv = 1.0f / s;
        for (int i = l; i < LSEQ; i += 32) pr[i] *= inv;
        __syncwarp();

        unsigned* hw = hist + w * 256;
        unsigned pref = 0; int need = TOPK;
        const unsigned pmasks[4] = {0u, 0xFF000000u, 0xFFFF0000u, 0xFFFFFF00u};
#pragma unroll
        for (int pass = 0; pass < 4; pass++) {
            const int shift = 24 - pass * 8;
            const unsigned pmask = pmasks[pass];
            for (int bi = l; bi < 256; bi += 32) hw[bi] = 0u;
            __syncwarp();
            for (int i = l; i < LSEQ; i += 32) {
                const unsigned u = __float_as_uint(pr[i]);
                if ((u & pmask) == pref) atomicAdd(&hw[(u >> shift) & 255], 1u);
            }
            __syncwarp();
            if (l == 0) {
                unsigned cum = 0; int d = 255;
                for (; d > 0; d--) {
                    const unsigned cc = hw[d];
                    if (cum + cc >= (unsigned)need) break;
                    cum += cc;
                }
                pref |= (unsigned)d << shift;
                need -= (int)cum;
            }
            pref = __shfl_sync(0xffffffffu, pref, 0);
            need = __shfl_sync(0xffffffffu, need, 0);
            __syncwarp();
        }
        const float thr = __uint_as_float(pref);
        for (int i = l; i < LSEQ; i += 32) { const float v = pr[i]; pr[i] = (v >= thr) ? v : 0.0f; }
    }
    __syncthreads();

    // ---- phase 3: ctx = P @ v, gate by q ----
    {
        const int g = tid & 15;          // dh slice g*4..+3
        const int s = tid >> 4;          // n slot (0..31)
        const float* vb = g_v + (size_t)bh * LSEQ * NDH + g * 4;
        ull acc[16][2];
#pragma unroll
        for (int r = 0; r < 16; r++) { acc[r][0] = 0ull; acc[r][1] = 0ull; }

#define PROC3(VV, N) do {                                                   \
        const ull v01 = pk2((VV).x, (VV).y);                                \
        const ull v23 = pk2((VV).z, (VV).w);                                \
        _Pragma("unroll")                                                   \
        for (int r = 0; r < 16; r++) {                                      \
            const float p = sP[r * PSTR + (N)];                             \
            const ull pp = pk2(p, p);                                       \
            fma2(acc[r][0], pp, v01);                                       \
            fma2(acc[r][1], pp, v23);                                       \
        } } while (0)

        float4 vv = *(const float4*)(vb + (size_t)s * NDH);
        int n = s;
        for (; n + 32 < LSEQ; n += 32) {
            const float4 nx = *(const float4*)(vb + (size_t)(n + 32) * NDH);
            PROC3(vv, n);
            vv = nx;
        }
        PROC3(vv, n);
#undef PROC3
        __syncthreads();                  // all reads of sP done

        float* sR = sm;                   // overlay partials on sP: [32][16][64]
#pragma unroll
        for (int r = 0; r < 16; r++) {
            float a0, a1, a2, a3;
            upk2(acc[r][0], a0, a1);
            upk2(acc[r][1], a2, a3);
            *(float4*)&sR[((s * 16 + r) << 6) + (g << 2)] = make_float4(a0, a1, a2, a3);
        }
        __syncthreads();

        for (int o = tid; o < 1024; o += 512) {
            float c = 0.0f;
#pragma unroll
            for (int s2 = 0; s2 < 32; s2++) c += sR[(s2 << 10) + o];
            const int r = o >> 6, dh = o & 63;
            c *= sQT[dh * 16 + r];
            g_ctx[((size_t)(b * LSEQ) + m0 + r) * ND + h * NDH + dh] = c;
        }
    }
}

// ---------------------------------------------------------------------------
extern "C" void kernel_launch(void* const* d_in, const int* in_sizes, int n_in,
                              void* d_out, int out_size)
{
    const float* q_in = (const float*)d_in[0];
    const float* k_in = (const float*)d_in[1];
    const float* Wq   = (const float*)d_in[2];
    const float* bq   = (const float*)d_in[3];
    const float* Wk   = (const float*)d_in[4];
    const float* bk   = (const float*)d_in[5];
    const float* Wv   = (const float*)d_in[6];
    const float* bv   = (const float*)d_in[7];
    const float* Wo   = (const float*)d_in[8];
    const float* bo   = (const float*)d_in[9];
    const int*   mask = (const int*)d_in[10];
    float* out = (float*)d_out;

    void *pq = 0, *pk = 0, *pv = 0, *pctx = 0;
    cudaGetSymbolAddress(&pq, g_q);
    cudaGetSymbolAddress(&pk, g_kT);
    cudaGetSymbolAddress(&pv, g_v);
    cudaGetSymbolAddress(&pctx, g_ctx);

    const int smemb = (16 * PSTR + 1024 + 16 * 256) * 4;   // 151808 B
    cudaFuncSetAttribute(fused_attn, cudaFuncAttributeMaxDynamicSharedMemorySize, smemb);

    const dim3 thr(256);

    proj_qkv<<<dim3(ND / 128, (NB * LSEQ) / 128, 3), thr>>>(
        q_in, k_in, Wq, bq, Wk, bk, Wv, bv,
        (float*)pq, (float*)pk, (float*)pv);

    fused_attn<<<dim3(LSEQ / 16, NBH), 512, smemb>>>(mask);

    out_proj<<<dim3(ND / 128, (NB * LSEQ) / 128), thr>>>(
        (const float*)pctx, Wo, bo, out);
}